// round 13
// baseline (speedup 1.0000x reference)
// R13: BK=64 GEMM (half the barriers, 4 ksub per iteration), unified 128B-row
// swizzled tiles, 2-stage 48KB static ring. Attention/LN unchanged from R12.
#include <cuda_runtime.h>
#include <cuda_bf16.h>
#include <math.h>
#include <stdint.h>

#define BATCH 32
#define HH 56
#define WW2 56
#define CC 192
#define HID 768
#define WS 7
#define SS 3
#define NH 6
#define HD 32
#define NTOK 49
#define NWIN 64
#define MROWS (BATCH*HH*WW2)
#define ROWS_PER_BATCH (NWIN*NTOK)

typedef __nv_bfloat16 bf16;
typedef __nv_bfloat162 bf162;

// ---------------- scratch ----------------
__device__ bf16  g_xn_h [MROWS*CC];
__device__ bf16  g_qkv_h[(long)MROWS*3*CC];
__device__ bf16  g_attn_h[MROWS*CC];
__device__ float g_y    [MROWS*CC];
__device__ bf16  g_xn2_h[MROWS*CC];
__device__ bf16  g_h_h  [(long)MROWS*HID];
__device__ bf16  g_wq[CC*3*CC];
__device__ bf16  g_wp[CC*CC];
__device__ bf16  g_w1[CC*HID];
__device__ bf16  g_w2[HID*CC];
__device__ float g_bias[4*NH*64*64];

__device__ __forceinline__ int win2img(int r) {
    int b   = r / ROWS_PER_BATCH;
    int rem = r - b * ROWS_PER_BATCH;
    int w   = rem / NTOK;
    int n   = rem - w * NTOK;
    int i = n / WS, j = n - WS * (n / WS);
    int hs = (w >> 3) * WS + i;
    int ws = (w & 7) * WS + j;
    int h  = hs + SS; if (h  >= HH)  h  -= HH;
    int wc = ws + SS; if (wc >= WW2) wc -= WW2;
    return (b * HH + h) * WW2 + wc;
}

// ---------------- fp32 -> bf16 conversion for all four weights ------------
#define WQ_N (CC*3*CC)
#define WP_N (CC*CC)
#define W1_N (CC*HID)
#define W2_N (HID*CC)
#define WTOT (WQ_N+WP_N+W1_N+W2_N)
__global__ void f2bf_all(const float* __restrict__ s0, const float* __restrict__ s1,
                         const float* __restrict__ s2, const float* __restrict__ s3,
                         bf16* d0, bf16* d1, bf16* d2, bf16* d3) {
    int i = blockIdx.x * 256 + threadIdx.x;
    if (i < WQ_N) { d0[i] = __float2bfloat16(s0[i]); return; }
    i -= WQ_N;
    if (i < WP_N) { d1[i] = __float2bfloat16(s1[i]); return; }
    i -= WP_N;
    if (i < W1_N) { d2[i] = __float2bfloat16(s2[i]); return; }
    i -= W1_N;
    if (i < W2_N) { d3[i] = __float2bfloat16(s3[i]); }
}

// ---------------- attention bias table ----------------
__global__ void bias_precompute(const float* __restrict__ rpb) {
    int idx = blockIdx.x * 256 + threadIdx.x;
    int cls = idx / (NH*4096);
    int rem = idx - cls*NH*4096;
    int h   = rem >> 12;
    int p   = rem & 4095;
    int n = p >> 6, m = p & 63;
    float v;
    if (m >= NTOK) v = -1e9f;
    else if (n >= NTOK) v = 0.f;
    else {
        int in_ = n / WS, jn = n % WS, im = m / WS, jm = m % WS;
        v = rpb[((in_-im+6)*13 + (jn-jm+6))*NH + h];
        int rE = cls >> 1, cE = cls & 1;
        int rn = rE ? (in_ < 4 ? 1 : 2) : 0;
        int cn = cE ? (jn  < 4 ? 1 : 2) : 0;
        int rm = rE ? (im  < 4 ? 1 : 2) : 0;
        int cm = cE ? (jm  < 4 ? 1 : 2) : 0;
        if (rn*3+cn != rm*3+cm) v -= 100.f;
    }
    g_bias[idx] = v;
}

// ---------------- LayerNorm ----------------
__global__ void ln_kernel(const float* __restrict__ x, const float* __restrict__ g,
                          const float* __restrict__ b, bf16* __restrict__ o) {
    int row  = blockIdx.x * 8 + (threadIdx.x >> 5);
    int lane = threadIdx.x & 31;
    const float* p = x + (long)row * CC;
    float v[6];
    float s = 0.f;
    #pragma unroll
    for (int i = 0; i < 6; i++) { v[i] = p[lane + 32*i]; s += v[i]; }
    #pragma unroll
    for (int off = 16; off; off >>= 1) s += __shfl_xor_sync(~0u, s, off);
    float mu = s * (1.f/192.f);
    float vs = 0.f;
    #pragma unroll
    for (int i = 0; i < 6; i++) { float d = v[i]-mu; vs += d*d; }
    #pragma unroll
    for (int off = 16; off; off >>= 1) vs += __shfl_xor_sync(~0u, vs, off);
    float r = rsqrtf(vs * (1.f/192.f) + 1e-5f);
    bf16* op = o + (long)row * CC;
    #pragma unroll
    for (int i = 0; i < 6; i++) {
        int c = lane + 32*i;
        op[c] = __float2bfloat16((v[i]-mu) * r * g[c] + b[c]);
    }
}

// ---------------- helpers ----------------
__device__ __forceinline__ void mma_bf16(float* c, const uint32_t* a, const uint32_t* b) {
    asm volatile("mma.sync.aligned.m16n8k16.row.col.f32.bf16.bf16.f32 "
        "{%0,%1,%2,%3},{%4,%5,%6,%7},{%8,%9},{%0,%1,%2,%3};"
        : "+f"(c[0]), "+f"(c[1]), "+f"(c[2]), "+f"(c[3])
        : "r"(a[0]), "r"(a[1]), "r"(a[2]), "r"(a[3]), "r"(b[0]), "r"(b[1]));
}
__device__ __forceinline__ void ldmx4(uint32_t* r, uint32_t addr) {
    asm volatile("ldmatrix.sync.aligned.m8n8.x4.shared.b16 {%0,%1,%2,%3}, [%4];"
        : "=r"(r[0]), "=r"(r[1]), "=r"(r[2]), "=r"(r[3]) : "r"(addr));
}
__device__ __forceinline__ void ldmx4t(uint32_t* r, uint32_t addr) {
    asm volatile("ldmatrix.sync.aligned.m8n8.x4.trans.shared.b16 {%0,%1,%2,%3}, [%4];"
        : "=r"(r[0]), "=r"(r[1]), "=r"(r[2]), "=r"(r[3]) : "r"(addr));
}
__device__ __forceinline__ void cp16(uint32_t smem, const void* g) {
    asm volatile("cp.async.cg.shared.global [%0], [%1], 16;" :: "r"(smem), "l"(g));
}
__device__ __forceinline__ uint32_t packbf(float lo, float hi) {
    bf162 t; t.x = __float2bfloat16(lo); t.y = __float2bfloat16(hi);
    return *(uint32_t*)&t;
}

// ---------------- bf16 mma GEMM: 128x64 block, BK=64, 2 warps x (64x64) ---
#define BM 128
#define BN 64
#define BK 64
#define A_BYTES (BM*128)     // 16384 per stage (row = 64 bf16 = 128B)
#define B_BYTES (BK*128)     // 8192 per stage (row = 64 bf16 = 128B)

enum { EPI_NONE = 0, EPI_GELU = 1, EPI_RES = 2, EPI_SCATTER_RES = 3 };

__device__ __forceinline__ float gelu_f(float x) {
    return 0.5f * x * (1.0f + erff(x * 0.70710678118654752f));
}

template<int EPI, bool GATHER_A, bool OUT_BF16>
__global__ void __launch_bounds__(64) tgemm(const bf16* __restrict__ A,
                                            const bf16* __restrict__ Bm,
                                            const float* __restrict__ bias,
                                            void* __restrict__ Cv,
                                            const float* __restrict__ resid,
                                            int N, int K) {
    __shared__ char smemA[2*A_BYTES];
    __shared__ char smemB[2*B_BYTES];
    const uint32_t sA = (uint32_t)__cvta_generic_to_shared(smemA);
    const uint32_t sB = (uint32_t)__cvta_generic_to_shared(smemB);
    const int tid = threadIdx.x, lane = tid & 31, warp = tid >> 5;
    const int m0 = blockIdx.y * BM;
    const int n0 = blockIdx.x * BN;

    // ---- load maps: 128B rows, chunk = tid&7, rows = (tid>>3) + 8v
    const int lr = tid >> 3;      // 0..7
    const int ch = tid & 7;       // 0..7
    const bf16* agp[16];
    uint32_t adst[16];
    #pragma unroll
    for (int v = 0; v < 16; v++) {
        int row = lr + 8*v;
        agp[v] = A + (long)(GATHER_A ? win2img(m0 + row) : (m0 + row)) * K + ch*8;
        adst[v] = row*128 + (uint32_t)((ch ^ (row & 7))*16);
    }
    const bf16* bgp[8];
    uint32_t bdst[8];
    #pragma unroll
    for (int v = 0; v < 8; v++) {
        int bk = lr + 8*v;
        bgp[v] = Bm + (long)bk * N + n0 + ch*8;
        bdst[v] = bk*128 + (uint32_t)((ch ^ (bk & 7))*16);
    }

    const int m_warp = warp * 64;     // warp tile 64 x 64

    float acc[4][8][4];
    #pragma unroll
    for (int i = 0; i < 4; i++)
        #pragma unroll
        for (int j = 0; j < 8; j++)
            #pragma unroll
            for (int l = 0; l < 4; l++) acc[i][j][l] = 0.f;

    const int nk = K / BK;    // 3 (K=192) or 12 (K=768)

    auto loadStage = [&](int s, int buf) {
        #pragma unroll
        for (int v = 0; v < 16; v++)
            cp16(sA + buf*A_BYTES + adst[v], agp[v] + s*BK);
        #pragma unroll
        for (int v = 0; v < 8; v++)
            cp16(sB + buf*B_BYTES + bdst[v], bgp[v] + (long)s*BK*N);
        asm volatile("cp.async.commit_group;" ::: "memory");
    };

    loadStage(0, 0);

    for (int it = 0; it < nk; ++it) {
        asm volatile("cp.async.wait_group 0;" ::: "memory");
        __syncthreads();
        // prefetch it+1 into the other buffer: it was read in it-1, and this
        // iteration's barrier proves all warps finished that compute.
        if (it + 1 < nk) loadStage(it + 1, (it + 1) & 1);

        const uint32_t aB = sA + (it & 1)*A_BYTES;
        const uint32_t bB = sB + (it & 1)*B_BYTES;
        #pragma unroll
        for (int ksub = 0; ksub < 4; ksub++) {
            uint32_t afr[4][4];
            #pragma unroll
            for (int mt = 0; mt < 4; mt++) {
                int row = m_warp + mt*16 + (lane & 15);
                int c2  = ksub*2 + (lane >> 4);
                ldmx4(afr[mt], aB + row*128 + ((c2 ^ (row & 7))*16));
            }
            uint32_t bfr[8][2];
            #pragma unroll
            for (int cg = 0; cg < 4; cg++) {
                int k  = ksub*16 + ((lane>>3)&1)*8 + (lane&7);
                int cn = cg*2 + (lane>>4);
                uint32_t r[4];
                ldmx4t(r, bB + k*128 + ((cn ^ (k&7))*16));
                bfr[cg*2+0][0] = r[0]; bfr[cg*2+0][1] = r[1];
                bfr[cg*2+1][0] = r[2]; bfr[cg*2+1][1] = r[3];
            }
            #pragma unroll
            for (int mt = 0; mt < 4; mt++)
                #pragma unroll
                for (int nt = 0; nt < 8; nt++)
                    mma_bf16(acc[mt][nt], afr[mt], bfr[nt]);
        }
    }

    // ---- epilogue: warp rows m_warp..m_warp+63, all 64 cols
    const int g  = lane >> 2;
    const int tg = lane & 3;
    float* Cf = (float*)Cv;
    bf16*  Cb = (bf16*)Cv;
    #pragma unroll
    for (int mt = 0; mt < 4; mt++) {
        #pragma unroll
        for (int rh = 0; rh < 2; rh++) {
            int m = m0 + m_warp + mt*16 + rh*8 + g;
            long crow = (EPI == EPI_SCATTER_RES) ? (long)win2img(m) : (long)m;
            #pragma unroll
            for (int nt = 0; nt < 8; nt++) {
                int col = n0 + nt*8 + tg*2;
                float2 bb = *(const float2*)(bias + col);
                float v0 = acc[mt][nt][rh*2 + 0] + bb.x;
                float v1 = acc[mt][nt][rh*2 + 1] + bb.y;
                if (EPI == EPI_GELU) { v0 = gelu_f(v0); v1 = gelu_f(v1); }
                if (EPI == EPI_RES || EPI == EPI_SCATTER_RES) {
                    float2 r2 = *(const float2*)(resid + crow * N + col);
                    v0 += r2.x; v1 += r2.y;
                }
                if (OUT_BF16) {
                    bf162 o; o.x = __float2bfloat16(v0); o.y = __float2bfloat16(v1);
                    *(bf162*)(Cb + crow * N + col) = o;
                } else {
                    float2 o2 = {v0, v1};
                    *(float2*)(Cf + crow * N + col) = o2;
                }
            }
        }
    }
}

// ---------------- tensor-core windowed attention (unchanged) --------------
#define BSTR 68

__global__ void __launch_bounds__(128) attn_kernel(const bf16* __restrict__ qkv,
                                                   bf16* __restrict__ out) {
    __shared__ __align__(16) bf16 sq[64*32];
    __shared__ __align__(16) bf16 sk[64*32];
    __shared__ __align__(16) bf16 sv[64*32];
    __shared__ __align__(16) float sbias[64*BSTR];

    const int tid = threadIdx.x, lane = tid & 31, wid = tid >> 5;
    const int win = blockIdx.x, h = blockIdx.y;
    const int w = win & 63;
    const int cls = (((w >> 3) == 7) ? 2 : 0) + (((w & 7) == 7) ? 1 : 0);
    const float* gb = g_bias + ((cls*NH + h) << 12);
    const long base = (long)win * NTOK;
    const float scale = 0.17677669529663687f;

    const uint32_t sqb = (uint32_t)__cvta_generic_to_shared(sq);
    const uint32_t skb = (uint32_t)__cvta_generic_to_shared(sk);
    const uint32_t svb = (uint32_t)__cvta_generic_to_shared(sv);

    #pragma unroll
    for (int i = 0; i < 2; i++) {
        int idx = tid + i*128;
        int n = idx >> 2, ch = idx & 3;
        uint4 zq = {0,0,0,0}, zk = {0,0,0,0}, zv = {0,0,0,0};
        if (n < NTOK) {
            const bf16* p = qkv + (base + n)*(3*CC) + h*HD + ch*8;
            zq = *(const uint4*)(p);
            zk = *(const uint4*)(p + CC);
            zv = *(const uint4*)(p + 2*CC);
        }
        uint32_t off = n*64 + ((ch ^ ((n>>1)&3))*16);
        *(uint4*)((char*)sq + off) = zq;
        *(uint4*)((char*)sk + off) = zk;
        *(uint4*)((char*)sv + off) = zv;
    }
    #pragma unroll
    for (int i = 0; i < 8; i++) {
        int idx = tid + i*128;
        int row = idx >> 4, c4 = idx & 15;
        *(float4*)&sbias[row*BSTR + c4*4] = *(const float4*)(gb + row*64 + c4*4);
    }
    __syncthreads();

    float s[8][4];
    #pragma unroll
    for (int i = 0; i < 8; i++)
        #pragma unroll
        for (int j = 0; j < 4; j++) s[i][j] = 0.f;

    #pragma unroll
    for (int ksub = 0; ksub < 2; ksub++) {
        uint32_t a[4];
        {
            int row = wid*16 + (lane & 15);
            int ch  = ksub*2 + (lane >> 4);
            ldmx4(a, sqb + row*64 + ((ch ^ ((row>>1)&3))*16));
        }
        #pragma unroll
        for (int bt = 0; bt < 4; bt++) {
            int n  = bt*16 + ((lane>>4)&1)*8 + (lane & 7);
            int ch = ksub*2 + ((lane>>3)&1);
            uint32_t r[4];
            ldmx4(r, skb + n*64 + ((ch ^ ((n>>1)&3))*16));
            uint32_t b0[2] = {r[0], r[1]}, b1[2] = {r[2], r[3]};
            mma_bf16(s[bt*2+0], a, b0);
            mma_bf16(s[bt*2+1], a, b1);
        }
    }

    const int g  = lane >> 2, tg = lane & 3;
    const int r0 = wid*16 + g, r1 = r0 + 8;
    float mx0 = -1e30f, mx1 = -1e30f;
    #pragma unroll
    for (int nt = 0; nt < 8; nt++) {
        float2 b0 = *(const float2*)&sbias[r0*BSTR + nt*8 + tg*2];
        float2 b1 = *(const float2*)&sbias[r1*BSTR + nt*8 + tg*2];
        s[nt][0] = fmaf(s[nt][0], scale, b0.x);
        s[nt][1] = fmaf(s[nt][1], scale, b0.y);
        s[nt][2] = fmaf(s[nt][2], scale, b1.x);
        s[nt][3] = fmaf(s[nt][3], scale, b1.y);
        mx0 = fmaxf(mx0, fmaxf(s[nt][0], s[nt][1]));
        mx1 = fmaxf(mx1, fmaxf(s[nt][2], s[nt][3]));
    }
    mx0 = fmaxf(mx0, __shfl_xor_sync(~0u, mx0, 1));
    mx0 = fmaxf(mx0, __shfl_xor_sync(~0u, mx0, 2));
    mx1 = fmaxf(mx1, __shfl_xor_sync(~0u, mx1, 1));
    mx1 = fmaxf(mx1, __shfl_xor_sync(~0u, mx1, 2));
    float sum0 = 0.f, sum1 = 0.f;
    #pragma unroll
    for (int nt = 0; nt < 8; nt++) {
        s[nt][0] = __expf(s[nt][0] - mx0);
        s[nt][1] = __expf(s[nt][1] - mx0);
        s[nt][2] = __expf(s[nt][2] - mx1);
        s[nt][3] = __expf(s[nt][3] - mx1);
        sum0 += s[nt][0] + s[nt][1];
        sum1 += s[nt][2] + s[nt][3];
    }
    sum0 += __shfl_xor_sync(~0u, sum0, 1);
    sum0 += __shfl_xor_sync(~0u, sum0, 2);
    sum1 += __shfl_xor_sync(~0u, sum1, 1);
    sum1 += __shfl_xor_sync(~0u, sum1, 2);
    const float inv0 = 1.f / sum0, inv1 = 1.f / sum1;

    uint32_t pk[4][4];
    #pragma unroll
    for (int kt = 0; kt < 4; kt++) {
        pk[kt][0] = packbf(s[2*kt  ][0], s[2*kt  ][1]);
        pk[kt][1] = packbf(s[2*kt  ][2], s[2*kt  ][3]);
        pk[kt][2] = packbf(s[2*kt+1][0], s[2*kt+1][1]);
        pk[kt][3] = packbf(s[2*kt+1][2], s[2*kt+1][3]);
    }

    float o[4][4];
    #pragma unroll
    for (int i = 0; i < 4; i++)
        #pragma unroll
        for (int j = 0; j < 4; j++) o[i][j] = 0.f;

    #pragma unroll
    for (int kt = 0; kt < 4; kt++) {
        #pragma unroll
        for (int pr = 0; pr < 2; pr++) {
            int k  = kt*16 + ((lane>>3)&1)*8 + (lane & 7);
            int cn = pr*2 + ((lane>>4)&1);
            uint32_t r[4];
            ldmx4t(r, svb + k*64 + ((cn ^ ((k>>1)&3))*16));
            uint32_t b0[2] = {r[0], r[1]}, b1[2] = {r[2], r[3]};
            mma_bf16(o[pr*2+0], pk[kt], b0);
            mma_bf16(o[pr*2+1], pk[kt], b1);
        }
    }

    #pragma unroll
    for (int nt = 0; nt < 4; nt++) {
        int col = h*HD + nt*8 + tg*2;
        if (r0 < NTOK) {
            bf162 t; t.x = __float2bfloat16(o[nt][0]*inv0); t.y = __float2bfloat16(o[nt][1]*inv0);
            *(bf162*)(out + (base + r0)*CC + col) = t;
        }
        if (r1 < NTOK) {
            bf162 t; t.x = __float2bfloat16(o[nt][2]*inv1); t.y = __float2bfloat16(o[nt][3]*inv1);
            *(bf162*)(out + (base + r1)*CC + col) = t;
        }
    }
}

// ---------------- launch ----------------
extern "C" void kernel_launch(void* const* d_in, const int* in_sizes, int n_in,
                              void* d_out, int out_size) {
    const float* x       = (const float*)d_in[0];
    const float* n1g     = (const float*)d_in[1];
    const float* n1b     = (const float*)d_in[2];
    const float* qkv_w   = (const float*)d_in[3];
    const float* qkv_b   = (const float*)d_in[4];
    const float* rpb     = (const float*)d_in[5];
    const float* proj_w  = (const float*)d_in[6];
    const float* proj_b  = (const float*)d_in[7];
    const float* n2g     = (const float*)d_in[8];
    const float* n2b     = (const float*)d_in[9];
    const float* fc1_w   = (const float*)d_in[10];
    const float* fc1_b   = (const float*)d_in[11];
    const float* fc2_w   = (const float*)d_in[12];
    const float* fc2_b   = (const float*)d_in[13];
    float* out = (float*)d_out;

    bf16 *xn, *qkv, *attn, *xn2, *hbuf, *wq, *wp, *w1, *w2;
    float *y;
    cudaGetSymbolAddress((void**)&xn,   g_xn_h);
    cudaGetSymbolAddress((void**)&qkv,  g_qkv_h);
    cudaGetSymbolAddress((void**)&attn, g_attn_h);
    cudaGetSymbolAddress((void**)&y,    g_y);
    cudaGetSymbolAddress((void**)&xn2,  g_xn2_h);
    cudaGetSymbolAddress((void**)&hbuf, g_h_h);
    cudaGetSymbolAddress((void**)&wq,   g_wq);
    cudaGetSymbolAddress((void**)&wp,   g_wp);
    cudaGetSymbolAddress((void**)&w1,   g_w1);
    cudaGetSymbolAddress((void**)&w2,   g_w2);

    f2bf_all<<<(WTOT+255)/256, 256>>>(qkv_w, proj_w, fc1_w, fc2_w, wq, wp, w1, w2);
    bias_precompute<<<(4*NH*4096)/256, 256>>>(rpb);

    const int mblk = MROWS / BM;   // 784

    ln_kernel<<<MROWS/8, 256>>>(x, n1g, n1b, xn);
    tgemm<EPI_NONE, true, true><<<dim3(3*CC/BN, mblk), 64>>>(xn, wq, qkv_b, qkv, nullptr, 3*CC, CC);
    attn_kernel<<<dim3(BATCH*NWIN, NH), 128>>>(qkv, attn);
    tgemm<EPI_SCATTER_RES, false, false><<<dim3(CC/BN, mblk), 64>>>(attn, wp, proj_b, y, x, CC, CC);
    ln_kernel<<<MROWS/8, 256>>>(y, n2g, n2b, xn2);
    tgemm<EPI_GELU, false, true><<<dim3(HID/BN, mblk), 64>>>(xn2, w1, fc1_b, hbuf, nullptr, HID, CC);
    tgemm<EPI_RES, false, false><<<dim3(CC/BN, mblk), 64>>>(hbuf, w2, fc2_b, out, y, CC, HID);
}

// round 14
// speedup vs baseline: 1.0254x; 1.0254x over previous
// R14: attention bias staged as bf16 and read direct-to-register (no 17KB smem
// staging; smem 29->12KB/block); prep kernels merged. GEMMs = R13 (verified).
#include <cuda_runtime.h>
#include <cuda_bf16.h>
#include <math.h>
#include <stdint.h>

#define BATCH 32
#define HH 56
#define WW2 56
#define CC 192
#define HID 768
#define WS 7
#define SS 3
#define NH 6
#define HD 32
#define NTOK 49
#define NWIN 64
#define MROWS (BATCH*HH*WW2)
#define ROWS_PER_BATCH (NWIN*NTOK)

typedef __nv_bfloat16 bf16;
typedef __nv_bfloat162 bf162;

// ---------------- scratch ----------------
__device__ bf16  g_xn_h [MROWS*CC];
__device__ bf16  g_qkv_h[(long)MROWS*3*CC];
__device__ bf16  g_attn_h[MROWS*CC];
__device__ float g_y    [MROWS*CC];
__device__ bf16  g_xn2_h[MROWS*CC];
__device__ bf16  g_h_h  [(long)MROWS*HID];
__device__ bf16  g_wq[CC*3*CC];
__device__ bf16  g_wp[CC*CC];
__device__ bf16  g_w1[CC*HID];
__device__ bf16  g_w2[HID*CC];
__device__ bf16  g_bias_h[4*NH*64*64];   // [class][head][64][64], bf16

__device__ __forceinline__ int win2img(int r) {
    int b   = r / ROWS_PER_BATCH;
    int rem = r - b * ROWS_PER_BATCH;
    int w   = rem / NTOK;
    int n   = rem - w * NTOK;
    int i = n / WS, j = n - WS * (n / WS);
    int hs = (w >> 3) * WS + i;
    int ws = (w & 7) * WS + j;
    int h  = hs + SS; if (h  >= HH)  h  -= HH;
    int wc = ws + SS; if (wc >= WW2) wc -= WW2;
    return (b * HH + h) * WW2 + wc;
}

// ------------- one prep kernel: weight bf16 convert + bias table ----------
#define WQ_N (CC*3*CC)
#define WP_N (CC*CC)
#define W1_N (CC*HID)
#define W2_N (HID*CC)
#define WTOT (WQ_N+WP_N+W1_N+W2_N)
#define BIAS_N (4*NH*64*64)
__global__ void prep_all(const float* __restrict__ s0, const float* __restrict__ s1,
                         const float* __restrict__ s2, const float* __restrict__ s3,
                         const float* __restrict__ rpb,
                         bf16* d0, bf16* d1, bf16* d2, bf16* d3) {
    int i = blockIdx.x * 256 + threadIdx.x;
    if (i < WQ_N) { d0[i] = __float2bfloat16(s0[i]); return; }
    i -= WQ_N;
    if (i < WP_N) { d1[i] = __float2bfloat16(s1[i]); return; }
    i -= WP_N;
    if (i < W1_N) { d2[i] = __float2bfloat16(s2[i]); return; }
    i -= W1_N;
    if (i < W2_N) { d3[i] = __float2bfloat16(s3[i]); return; }
    i -= W2_N;
    if (i < BIAS_N) {
        int cls = i / (NH*4096);
        int rem = i - cls*NH*4096;
        int h   = rem >> 12;
        int p   = rem & 4095;
        int n = p >> 6, m = p & 63;
        float v;
        if (m >= NTOK) v = -1e9f;
        else if (n >= NTOK) v = 0.f;
        else {
            int in_ = n / WS, jn = n % WS, im = m / WS, jm = m % WS;
            v = rpb[((in_-im+6)*13 + (jn-jm+6))*NH + h];
            int rE = cls >> 1, cE = cls & 1;
            int rn = rE ? (in_ < 4 ? 1 : 2) : 0;
            int cn = cE ? (jn  < 4 ? 1 : 2) : 0;
            int rm = rE ? (im  < 4 ? 1 : 2) : 0;
            int cm = cE ? (jm  < 4 ? 1 : 2) : 0;
            if (rn*3+cn != rm*3+cm) v -= 100.f;
        }
        g_bias_h[i] = __float2bfloat16(v);
    }
}

// ---------------- LayerNorm ----------------
__global__ void ln_kernel(const float* __restrict__ x, const float* __restrict__ g,
                          const float* __restrict__ b, bf16* __restrict__ o) {
    int row  = blockIdx.x * 8 + (threadIdx.x >> 5);
    int lane = threadIdx.x & 31;
    const float* p = x + (long)row * CC;
    float v[6];
    float s = 0.f;
    #pragma unroll
    for (int i = 0; i < 6; i++) { v[i] = p[lane + 32*i]; s += v[i]; }
    #pragma unroll
    for (int off = 16; off; off >>= 1) s += __shfl_xor_sync(~0u, s, off);
    float mu = s * (1.f/192.f);
    float vs = 0.f;
    #pragma unroll
    for (int i = 0; i < 6; i++) { float d = v[i]-mu; vs += d*d; }
    #pragma unroll
    for (int off = 16; off; off >>= 1) vs += __shfl_xor_sync(~0u, vs, off);
    float r = rsqrtf(vs * (1.f/192.f) + 1e-5f);
    bf16* op = o + (long)row * CC;
    #pragma unroll
    for (int i = 0; i < 6; i++) {
        int c = lane + 32*i;
        op[c] = __float2bfloat16((v[i]-mu) * r * g[c] + b[c]);
    }
}

// ---------------- helpers ----------------
__device__ __forceinline__ void mma_bf16(float* c, const uint32_t* a, const uint32_t* b) {
    asm volatile("mma.sync.aligned.m16n8k16.row.col.f32.bf16.bf16.f32 "
        "{%0,%1,%2,%3},{%4,%5,%6,%7},{%8,%9},{%0,%1,%2,%3};"
        : "+f"(c[0]), "+f"(c[1]), "+f"(c[2]), "+f"(c[3])
        : "r"(a[0]), "r"(a[1]), "r"(a[2]), "r"(a[3]), "r"(b[0]), "r"(b[1]));
}
__device__ __forceinline__ void ldmx4(uint32_t* r, uint32_t addr) {
    asm volatile("ldmatrix.sync.aligned.m8n8.x4.shared.b16 {%0,%1,%2,%3}, [%4];"
        : "=r"(r[0]), "=r"(r[1]), "=r"(r[2]), "=r"(r[3]) : "r"(addr));
}
__device__ __forceinline__ void ldmx4t(uint32_t* r, uint32_t addr) {
    asm volatile("ldmatrix.sync.aligned.m8n8.x4.trans.shared.b16 {%0,%1,%2,%3}, [%4];"
        : "=r"(r[0]), "=r"(r[1]), "=r"(r[2]), "=r"(r[3]) : "r"(addr));
}
__device__ __forceinline__ void cp16(uint32_t smem, const void* g) {
    asm volatile("cp.async.cg.shared.global [%0], [%1], 16;" :: "r"(smem), "l"(g));
}
__device__ __forceinline__ uint32_t packbf(float lo, float hi) {
    bf162 t; t.x = __float2bfloat16(lo); t.y = __float2bfloat16(hi);
    return *(uint32_t*)&t;
}

// ---------------- bf16 mma GEMM: 128x64 block, BK=64, 2 warps x (64x64) ---
#define BM 128
#define BN 64
#define BK 64
#define A_BYTES (BM*128)
#define B_BYTES (BK*128)

enum { EPI_NONE = 0, EPI_GELU = 1, EPI_RES = 2, EPI_SCATTER_RES = 3 };

__device__ __forceinline__ float gelu_f(float x) {
    return 0.5f * x * (1.0f + erff(x * 0.70710678118654752f));
}

template<int EPI, bool GATHER_A, bool OUT_BF16>
__global__ void __launch_bounds__(64) tgemm(const bf16* __restrict__ A,
                                            const bf16* __restrict__ Bm,
                                            const float* __restrict__ bias,
                                            void* __restrict__ Cv,
                                            const float* __restrict__ resid,
                                            int N, int K) {
    __shared__ char smemA[2*A_BYTES];
    __shared__ char smemB[2*B_BYTES];
    const uint32_t sA = (uint32_t)__cvta_generic_to_shared(smemA);
    const uint32_t sB = (uint32_t)__cvta_generic_to_shared(smemB);
    const int tid = threadIdx.x, lane = tid & 31, warp = tid >> 5;
    const int m0 = blockIdx.y * BM;
    const int n0 = blockIdx.x * BN;

    const int lr = tid >> 3;
    const int ch = tid & 7;
    const bf16* agp[16];
    uint32_t adst[16];
    #pragma unroll
    for (int v = 0; v < 16; v++) {
        int row = lr + 8*v;
        agp[v] = A + (long)(GATHER_A ? win2img(m0 + row) : (m0 + row)) * K + ch*8;
        adst[v] = row*128 + (uint32_t)((ch ^ (row & 7))*16);
    }
    const bf16* bgp[8];
    uint32_t bdst[8];
    #pragma unroll
    for (int v = 0; v < 8; v++) {
        int bk = lr + 8*v;
        bgp[v] = Bm + (long)bk * N + n0 + ch*8;
        bdst[v] = bk*128 + (uint32_t)((ch ^ (bk & 7))*16);
    }

    const int m_warp = warp * 64;

    float acc[4][8][4];
    #pragma unroll
    for (int i = 0; i < 4; i++)
        #pragma unroll
        for (int j = 0; j < 8; j++)
            #pragma unroll
            for (int l = 0; l < 4; l++) acc[i][j][l] = 0.f;

    const int nk = K / BK;

    auto loadStage = [&](int s, int buf) {
        #pragma unroll
        for (int v = 0; v < 16; v++)
            cp16(sA + buf*A_BYTES + adst[v], agp[v] + s*BK);
        #pragma unroll
        for (int v = 0; v < 8; v++)
            cp16(sB + buf*B_BYTES + bdst[v], bgp[v] + (long)s*BK*N);
        asm volatile("cp.async.commit_group;" ::: "memory");
    };

    loadStage(0, 0);

    for (int it = 0; it < nk; ++it) {
        asm volatile("cp.async.wait_group 0;" ::: "memory");
        __syncthreads();
        if (it + 1 < nk) loadStage(it + 1, (it + 1) & 1);

        const uint32_t aB = sA + (it & 1)*A_BYTES;
        const uint32_t bB = sB + (it & 1)*B_BYTES;
        #pragma unroll
        for (int ksub = 0; ksub < 4; ksub++) {
            uint32_t afr[4][4];
            #pragma unroll
            for (int mt = 0; mt < 4; mt++) {
                int row = m_warp + mt*16 + (lane & 15);
                int c2  = ksub*2 + (lane >> 4);
                ldmx4(afr[mt], aB + row*128 + ((c2 ^ (row & 7))*16));
            }
            uint32_t bfr[8][2];
            #pragma unroll
            for (int cg = 0; cg < 4; cg++) {
                int k  = ksub*16 + ((lane>>3)&1)*8 + (lane&7);
                int cn = cg*2 + (lane>>4);
                uint32_t r[4];
                ldmx4t(r, bB + k*128 + ((cn ^ (k&7))*16));
                bfr[cg*2+0][0] = r[0]; bfr[cg*2+0][1] = r[1];
                bfr[cg*2+1][0] = r[2]; bfr[cg*2+1][1] = r[3];
            }
            #pragma unroll
            for (int mt = 0; mt < 4; mt++)
                #pragma unroll
                for (int nt = 0; nt < 8; nt++)
                    mma_bf16(acc[mt][nt], afr[mt], bfr[nt]);
        }
    }

    const int g  = lane >> 2;
    const int tg = lane & 3;
    float* Cf = (float*)Cv;
    bf16*  Cb = (bf16*)Cv;
    #pragma unroll
    for (int mt = 0; mt < 4; mt++) {
        #pragma unroll
        for (int rh = 0; rh < 2; rh++) {
            int m = m0 + m_warp + mt*16 + rh*8 + g;
            long crow = (EPI == EPI_SCATTER_RES) ? (long)win2img(m) : (long)m;
            #pragma unroll
            for (int nt = 0; nt < 8; nt++) {
                int col = n0 + nt*8 + tg*2;
                float2 bb = *(const float2*)(bias + col);
                float v0 = acc[mt][nt][rh*2 + 0] + bb.x;
                float v1 = acc[mt][nt][rh*2 + 1] + bb.y;
                if (EPI == EPI_GELU) { v0 = gelu_f(v0); v1 = gelu_f(v1); }
                if (EPI == EPI_RES || EPI == EPI_SCATTER_RES) {
                    float2 r2 = *(const float2*)(resid + crow * N + col);
                    v0 += r2.x; v1 += r2.y;
                }
                if (OUT_BF16) {
                    bf162 o; o.x = __float2bfloat16(v0); o.y = __float2bfloat16(v1);
                    *(bf162*)(Cb + crow * N + col) = o;
                } else {
                    float2 o2 = {v0, v1};
                    *(float2*)(Cf + crow * N + col) = o2;
                }
            }
        }
    }
}

// -------- tensor-core windowed attention: direct bf16 bias, 12KB smem -----
__global__ void __launch_bounds__(128) attn_kernel(const bf16* __restrict__ qkv,
                                                   bf16* __restrict__ out) {
    __shared__ __align__(16) bf16 sq[64*32];
    __shared__ __align__(16) bf16 sk[64*32];
    __shared__ __align__(16) bf16 sv[64*32];

    const int tid = threadIdx.x, lane = tid & 31, wid = tid >> 5;
    const int win = blockIdx.x, h = blockIdx.y;
    const int w = win & 63;
    const int cls = (((w >> 3) == 7) ? 2 : 0) + (((w & 7) == 7) ? 1 : 0);
    const bf16* gb = g_bias_h + ((cls*NH + h) << 12);
    const long base = (long)win * NTOK;
    const float scale = 0.17677669529663687f;

    const uint32_t sqb = (uint32_t)__cvta_generic_to_shared(sq);
    const uint32_t skb = (uint32_t)__cvta_generic_to_shared(sk);
    const uint32_t svb = (uint32_t)__cvta_generic_to_shared(sv);

    #pragma unroll
    for (int i = 0; i < 2; i++) {
        int idx = tid + i*128;
        int n = idx >> 2, ch = idx & 3;
        uint4 zq = {0,0,0,0}, zk = {0,0,0,0}, zv = {0,0,0,0};
        if (n < NTOK) {
            const bf16* p = qkv + (base + n)*(3*CC) + h*HD + ch*8;
            zq = *(const uint4*)(p);
            zk = *(const uint4*)(p + CC);
            zv = *(const uint4*)(p + 2*CC);
        }
        uint32_t off = n*64 + ((ch ^ ((n>>1)&3))*16);
        *(uint4*)((char*)sq + off) = zq;
        *(uint4*)((char*)sk + off) = zk;
        *(uint4*)((char*)sv + off) = zv;
    }
    __syncthreads();

    float s[8][4];
    #pragma unroll
    for (int i = 0; i < 8; i++)
        #pragma unroll
        for (int j = 0; j < 4; j++) s[i][j] = 0.f;

    #pragma unroll
    for (int ksub = 0; ksub < 2; ksub++) {
        uint32_t a[4];
        {
            int row = wid*16 + (lane & 15);
            int ch  = ksub*2 + (lane >> 4);
            ldmx4(a, sqb + row*64 + ((ch ^ ((row>>1)&3))*16));
        }
        #pragma unroll
        for (int bt = 0; bt < 4; bt++) {
            int n  = bt*16 + ((lane>>4)&1)*8 + (lane & 7);
            int ch = ksub*2 + ((lane>>3)&1);
            uint32_t r[4];
            ldmx4(r, skb + n*64 + ((ch ^ ((n>>1)&3))*16));
            uint32_t b0[2] = {r[0], r[1]}, b1[2] = {r[2], r[3]};
            mma_bf16(s[bt*2+0], a, b0);
            mma_bf16(s[bt*2+1], a, b1);
        }
    }

    // ---- scale + bias (direct bf16 reads) + softmax
    const int g  = lane >> 2, tg = lane & 3;
    const int r0 = wid*16 + g, r1 = r0 + 8;
    const bf16* gb0 = gb + r0*64 + tg*2;
    const bf16* gb1 = gb + r1*64 + tg*2;
    float mx0 = -1e30f, mx1 = -1e30f;
    #pragma unroll
    for (int nt = 0; nt < 8; nt++) {
        bf162 bb0 = *(const bf162*)(gb0 + nt*8);
        bf162 bb1 = *(const bf162*)(gb1 + nt*8);
        s[nt][0] = fmaf(s[nt][0], scale, __bfloat162float(bb0.x));
        s[nt][1] = fmaf(s[nt][1], scale, __bfloat162float(bb0.y));
        s[nt][2] = fmaf(s[nt][2], scale, __bfloat162float(bb1.x));
        s[nt][3] = fmaf(s[nt][3], scale, __bfloat162float(bb1.y));
        mx0 = fmaxf(mx0, fmaxf(s[nt][0], s[nt][1]));
        mx1 = fmaxf(mx1, fmaxf(s[nt][2], s[nt][3]));
    }
    mx0 = fmaxf(mx0, __shfl_xor_sync(~0u, mx0, 1));
    mx0 = fmaxf(mx0, __shfl_xor_sync(~0u, mx0, 2));
    mx1 = fmaxf(mx1, __shfl_xor_sync(~0u, mx1, 1));
    mx1 = fmaxf(mx1, __shfl_xor_sync(~0u, mx1, 2));
    float sum0 = 0.f, sum1 = 0.f;
    #pragma unroll
    for (int nt = 0; nt < 8; nt++) {
        s[nt][0] = __expf(s[nt][0] - mx0);
        s[nt][1] = __expf(s[nt][1] - mx0);
        s[nt][2] = __expf(s[nt][2] - mx1);
        s[nt][3] = __expf(s[nt][3] - mx1);
        sum0 += s[nt][0] + s[nt][1];
        sum1 += s[nt][2] + s[nt][3];
    }
    sum0 += __shfl_xor_sync(~0u, sum0, 1);
    sum0 += __shfl_xor_sync(~0u, sum0, 2);
    sum1 += __shfl_xor_sync(~0u, sum1, 1);
    sum1 += __shfl_xor_sync(~0u, sum1, 2);
    const float inv0 = 1.f / sum0, inv1 = 1.f / sum1;

    uint32_t pk[4][4];
    #pragma unroll
    for (int kt = 0; kt < 4; kt++) {
        pk[kt][0] = packbf(s[2*kt  ][0], s[2*kt  ][1]);
        pk[kt][1] = packbf(s[2*kt  ][2], s[2*kt  ][3]);
        pk[kt][2] = packbf(s[2*kt+1][0], s[2*kt+1][1]);
        pk[kt][3] = packbf(s[2*kt+1][2], s[2*kt+1][3]);
    }

    float o[4][4];
    #pragma unroll
    for (int i = 0; i < 4; i++)
        #pragma unroll
        for (int j = 0; j < 4; j++) o[i][j] = 0.f;

    #pragma unroll
    for (int kt = 0; kt < 4; kt++) {
        #pragma unroll
        for (int pr = 0; pr < 2; pr++) {
            int k  = kt*16 + ((lane>>3)&1)*8 + (lane & 7);
            int cn = pr*2 + ((lane>>4)&1);
            uint32_t r[4];
            ldmx4t(r, svb + k*64 + ((cn ^ ((k>>1)&3))*16));
            uint32_t b0[2] = {r[0], r[1]}, b1[2] = {r[2], r[3]};
            mma_bf16(o[pr*2+0], pk[kt], b0);
            mma_bf16(o[pr*2+1], pk[kt], b1);
        }
    }

    #pragma unroll
    for (int nt = 0; nt < 4; nt++) {
        int col = h*HD + nt*8 + tg*2;
        if (r0 < NTOK) {
            bf162 t; t.x = __float2bfloat16(o[nt][0]*inv0); t.y = __float2bfloat16(o[nt][1]*inv0);
            *(bf162*)(out + (base + r0)*CC + col) = t;
        }
        if (r1 < NTOK) {
            bf162 t; t.x = __float2bfloat16(o[nt][2]*inv1); t.y = __float2bfloat16(o[nt][3]*inv1);
            *(bf162*)(out + (base + r1)*CC + col) = t;
        }
    }
}

// ---------------- launch ----------------
extern "C" void kernel_launch(void* const* d_in, const int* in_sizes, int n_in,
                              void* d_out, int out_size) {
    const float* x       = (const float*)d_in[0];
    const float* n1g     = (const float*)d_in[1];
    const float* n1b     = (const float*)d_in[2];
    const float* qkv_w   = (const float*)d_in[3];
    const float* qkv_b   = (const float*)d_in[4];
    const float* rpb     = (const float*)d_in[5];
    const float* proj_w  = (const float*)d_in[6];
    const float* proj_b  = (const float*)d_in[7];
    const float* n2g     = (const float*)d_in[8];
    const float* n2b     = (const float*)d_in[9];
    const float* fc1_w   = (const float*)d_in[10];
    const float* fc1_b   = (const float*)d_in[11];
    const float* fc2_w   = (const float*)d_in[12];
    const float* fc2_b   = (const float*)d_in[13];
    float* out = (float*)d_out;

    bf16 *xn, *qkv, *attn, *xn2, *hbuf, *wq, *wp, *w1, *w2;
    float *y;
    cudaGetSymbolAddress((void**)&xn,   g_xn_h);
    cudaGetSymbolAddress((void**)&qkv,  g_qkv_h);
    cudaGetSymbolAddress((void**)&attn, g_attn_h);
    cudaGetSymbolAddress((void**)&y,    g_y);
    cudaGetSymbolAddress((void**)&xn2,  g_xn2_h);
    cudaGetSymbolAddress((void**)&hbuf, g_h_h);
    cudaGetSymbolAddress((void**)&wq,   g_wq);
    cudaGetSymbolAddress((void**)&wp,   g_wp);
    cudaGetSymbolAddress((void**)&w1,   g_w1);
    cudaGetSymbolAddress((void**)&w2,   g_w2);

    prep_all<<<(WTOT+BIAS_N+255)/256, 256>>>(qkv_w, proj_w, fc1_w, fc2_w, rpb,
                                             wq, wp, w1, w2);

    const int mblk = MROWS / BM;   // 784

    ln_kernel<<<MROWS/8, 256>>>(x, n1g, n1b, xn);
    tgemm<EPI_NONE, true, true><<<dim3(3*CC/BN, mblk), 64>>>(xn, wq, qkv_b, qkv, nullptr, 3*CC, CC);
    attn_kernel<<<dim3(BATCH*NWIN, NH), 128>>>(qkv, attn);
    tgemm<EPI_SCATTER_RES, false, false><<<dim3(CC/BN, mblk), 64>>>(attn, wp, proj_b, y, x, CC, CC);
    ln_kernel<<<MROWS/8, 256>>>(y, n2g, n2b, xn2);
    tgemm<EPI_GELU, false, true><<<dim3(HID/BN, mblk), 64>>>(xn2, w1, fc1_b, hbuf, nullptr, HID, CC);
    tgemm<EPI_RES, false, false><<<dim3(CC/BN, mblk), 64>>>(hbuf, w2, fc2_b, out, y, CC, HID);
}